// round 6
// baseline (speedup 1.0000x reference)
#include <cuda_runtime.h>

// Problem constants (shapes fixed by the dataset)
#define NMAX 50000
#define EMAX 1600000
#define KDIM 128          // inner dim of every GEMM (IN = H = 128)
#define HMAX 128
static __device__ __constant__ float c_eps = 1e-5f;

// ---------------- scratch (static device globals; no allocs allowed) -------
__device__ int   g_deg[NMAX];
__device__ int   g_rowptr[NMAX + 1];
__device__ int   g_cursor[NMAX];
__device__ int   g_csr[EMAX];
__device__ float g_hl[NMAX * HMAX];
__device__ float g_hr[NMAX * HMAX];
__device__ float g_y [NMAX * HMAX];
__device__ float g_sum[HMAX];
__device__ float g_sq [HMAX];
__device__ float g_scale[HMAX];
__device__ float g_shift[HMAX];

// ---------------- CSR construction -----------------------------------------
__global__ void k_zero(int n) {
    int i = blockIdx.x * blockDim.x + threadIdx.x;
    if (i < n) { g_deg[i] = 0; g_cursor[i] = 0; }
    if (i < HMAX) { g_sum[i] = 0.f; g_sq[i] = 0.f; }
}

__global__ void k_hist(const int* __restrict__ dst, int e) {
    int i = blockIdx.x * blockDim.x + threadIdx.x;
    if (i < e) atomicAdd(&g_deg[dst[i]], 1);
}

// single-block exclusive scan over g_deg -> g_rowptr
__global__ void k_scan(int n) {
    __shared__ int s[1024];
    __shared__ int carry_s;
    int t = threadIdx.x;
    if (t == 0) carry_s = 0;
    __syncthreads();
    for (int base = 0; base < n; base += 1024) {
        int v = (base + t < n) ? g_deg[base + t] : 0;
        s[t] = v;
        __syncthreads();
        for (int off = 1; off < 1024; off <<= 1) {
            int x = (t >= off) ? s[t - off] : 0;
            __syncthreads();
            s[t] += x;
            __syncthreads();
        }
        int incl  = s[t];
        int carry = carry_s;
        if (base + t < n) g_rowptr[base + t] = carry + incl - v;
        __syncthreads();
        if (t == 1023) carry_s = carry + incl;
        __syncthreads();
    }
    if (t == 0) g_rowptr[n] = carry_s;
}

__global__ void k_fill(const int* __restrict__ src, const int* __restrict__ dst, int e) {
    int i = blockIdx.x * blockDim.x + threadIdx.x;
    if (i < e) {
        int d = dst[i];
        int p = atomicAdd(&g_cursor[d], 1);
        g_csr[g_rowptr[d] + p] = src[i];
    }
}

// ---------------- fused dual GEMM ------------------------------------------
// hl = act(X) @ Wl^T ; hr = act(X) @ Wr^T + bias
// act(x) = relu(x*scale[k] + shift[k]) when scale != null (previous layer's
// BN+ReLU applied on load), else identity.
// Block tile: 128 rows x HOUT cols. Thread tile 8 x TN x 2. KT=16 (smem 25 KB).
// Register double-buffering: next chunk's global loads are issued right after
// the first barrier and overlap the FMA loop on the current smem tile.
template <int HOUT>
__global__ void __launch_bounds__(256)
k_gemm2(const float* __restrict__ X,
        const float* __restrict__ Wl, const float* __restrict__ Wr,
        const float* __restrict__ bias,
        const float* __restrict__ scale, const float* __restrict__ shift,
        float* __restrict__ hl, float* __restrict__ hr, int n)
{
    constexpr int TN = HOUT / 16;     // 8 (HOUT=128) or 4 (HOUT=64)
    constexpr int KT = 16;
    constexpr int XS = 128 + 4;       // k-major row stride for Xs
    constexpr int WS = HOUT + 4;      // k-major row stride for W tiles
    constexpr int WLN = HOUT / 64;    // W-load iterations (2 or 1)
    __shared__ float Xs [KT * XS];    // Xs[kk][row]   16*132*4 = 8448 B
    __shared__ float Wsl[KT * WS];
    __shared__ float Wsr[KT * WS];

    const int t  = threadIdx.x;
    const int cg = t & 15;            // column group (TN cols)
    const int rg = t >> 4;            // row group (8 rows)
    const int r0 = blockIdx.x * 128;

    // precomputed load coordinates
    int xrow[2], xq[2];
#pragma unroll
    for (int l = 0; l < 2; l++) { int f = t + l * 256; xrow[l] = f >> 2; xq[l] = f & 3; }
    int wc[WLN], wq[WLN];
#pragma unroll
    for (int l = 0; l < WLN; l++) { int f = t + l * 256; wc[l] = f >> 2; wq[l] = f & 3; }

    float acc_l[8][TN], acc_r[8][TN];
#pragma unroll
    for (int i = 0; i < 8; i++)
#pragma unroll
        for (int j = 0; j < TN; j++) { acc_l[i][j] = 0.f; acc_r[i][j] = 0.f; }

    float4 xv[2], wlv[WLN], wrv[WLN];

    // ---- prologue: load chunk 0 into registers
#pragma unroll
    for (int l = 0; l < 2; l++) {
        int gr = r0 + xrow[l];
        xv[l] = make_float4(0.f, 0.f, 0.f, 0.f);
        if (gr < n) xv[l] = *(const float4*)(X + (size_t)gr * KDIM + xq[l] * 4);
    }
#pragma unroll
    for (int l = 0; l < WLN; l++) {
        wlv[l] = *(const float4*)(Wl + (size_t)wc[l] * KDIM + wq[l] * 4);
        wrv[l] = *(const float4*)(Wr + (size_t)wc[l] * KDIM + wq[l] * 4);
    }

    for (int k0 = 0; k0 < KDIM; k0 += KT) {
        // ---- store current chunk's registers into smem (BN+ReLU fused on X)
#pragma unroll
        for (int l = 0; l < 2; l++) {
            float4 v = xv[l];
            if (scale) {
                int kb = k0 + xq[l] * 4;
                v.x = fmaxf(0.f, v.x * scale[kb + 0] + shift[kb + 0]);
                v.y = fmaxf(0.f, v.y * scale[kb + 1] + shift[kb + 1]);
                v.z = fmaxf(0.f, v.z * scale[kb + 2] + shift[kb + 2]);
                v.w = fmaxf(0.f, v.w * scale[kb + 3] + shift[kb + 3]);
            }
            int row = xrow[l], q = xq[l];
            Xs[(q * 4 + 0) * XS + row] = v.x;
            Xs[(q * 4 + 1) * XS + row] = v.y;
            Xs[(q * 4 + 2) * XS + row] = v.z;
            Xs[(q * 4 + 3) * XS + row] = v.w;
        }
#pragma unroll
        for (int l = 0; l < WLN; l++) {
            int c = wc[l], q = wq[l];
            Wsl[(q * 4 + 0) * WS + c] = wlv[l].x;
            Wsl[(q * 4 + 1) * WS + c] = wlv[l].y;
            Wsl[(q * 4 + 2) * WS + c] = wlv[l].z;
            Wsl[(q * 4 + 3) * WS + c] = wlv[l].w;
            Wsr[(q * 4 + 0) * WS + c] = wrv[l].x;
            Wsr[(q * 4 + 1) * WS + c] = wrv[l].y;
            Wsr[(q * 4 + 2) * WS + c] = wrv[l].z;
            Wsr[(q * 4 + 3) * WS + c] = wrv[l].w;
        }
        __syncthreads();

        // ---- prefetch NEXT chunk into registers (overlaps FMA loop below)
        int kn = k0 + KT;
        if (kn < KDIM) {
#pragma unroll
            for (int l = 0; l < 2; l++) {
                int gr = r0 + xrow[l];
                xv[l] = make_float4(0.f, 0.f, 0.f, 0.f);
                if (gr < n) xv[l] = *(const float4*)(X + (size_t)gr * KDIM + kn + xq[l] * 4);
            }
#pragma unroll
            for (int l = 0; l < WLN; l++) {
                wlv[l] = *(const float4*)(Wl + (size_t)wc[l] * KDIM + kn + wq[l] * 4);
                wrv[l] = *(const float4*)(Wr + (size_t)wc[l] * KDIM + kn + wq[l] * 4);
            }
        }

        // ---- FMA loop over the current smem tile
#pragma unroll
        for (int kk = 0; kk < KT; kk++) {
            float a[8];
            const float4* ap = (const float4*)(Xs + kk * XS + rg * 8);
            float4 a0 = ap[0], a1 = ap[1];
            a[0]=a0.x; a[1]=a0.y; a[2]=a0.z; a[3]=a0.w;
            a[4]=a1.x; a[5]=a1.y; a[6]=a1.z; a[7]=a1.w;
            float wl[TN], wr[TN];
            const float4* wlp = (const float4*)(Wsl + kk * WS + cg * TN);
            const float4* wrp = (const float4*)(Wsr + kk * WS + cg * TN);
#pragma unroll
            for (int j4 = 0; j4 < TN / 4; j4++) {
                float4 v = wlp[j4];
                wl[j4*4+0]=v.x; wl[j4*4+1]=v.y; wl[j4*4+2]=v.z; wl[j4*4+3]=v.w;
                float4 u = wrp[j4];
                wr[j4*4+0]=u.x; wr[j4*4+1]=u.y; wr[j4*4+2]=u.z; wr[j4*4+3]=u.w;
            }
#pragma unroll
            for (int i = 0; i < 8; i++)
#pragma unroll
                for (int j = 0; j < TN; j++) {
                    acc_l[i][j] = fmaf(a[i], wl[j], acc_l[i][j]);
                    acc_r[i][j] = fmaf(a[i], wr[j], acc_r[i][j]);
                }
        }
        __syncthreads();
    }

    // --- epilogue
#pragma unroll
    for (int i = 0; i < 8; i++) {
        int row = r0 + rg * 8 + i;
        if (row < n) {
#pragma unroll
            for (int j4 = 0; j4 < TN / 4; j4++) {
                int c = cg * TN + j4 * 4;
                float4 v;
                v.x = acc_l[i][j4*4+0]; v.y = acc_l[i][j4*4+1];
                v.z = acc_l[i][j4*4+2]; v.w = acc_l[i][j4*4+3];
                *(float4*)(hl + (size_t)row * HOUT + c) = v;
                float4 u;
                u.x = acc_r[i][j4*4+0] + bias[c + 0];
                u.y = acc_r[i][j4*4+1] + bias[c + 1];
                u.z = acc_r[i][j4*4+2] + bias[c + 2];
                u.w = acc_r[i][j4*4+3] + bias[c + 3];
                *(float4*)(hr + (size_t)row * HOUT + c) = u;
            }
        }
    }
}

// ---------------- aggregation: y = mean_nbr(hl) + hr, optional BN stats ----
// warp per node; lane owns HC/32 channels (float4 / float2).
// 8-deep main loop, 4-deep mid loop, serial tail.
template <int HC, bool STATS>
__global__ void __launch_bounds__(512)
k_agg(const float* __restrict__ hl, const float* __restrict__ hr,
      float* __restrict__ y, int n)
{
    constexpr int VEC = HC / 32;   // 4 or 2
    __shared__ float ssum[HC];
    __shared__ float ssq [HC];
    const int t    = threadIdx.x;
    const int lane = t & 31;
    const int w    = t >> 5;

    if (STATS) {
        if (t < HC) { ssum[t] = 0.f; ssq[t] = 0.f; }
        __syncthreads();
    }

    int node = blockIdx.x * 16 + w;
    if (node < n) {
        int beg = g_rowptr[node];
        int end = g_rowptr[node + 1];
        const float* base = hl + lane * VEC;

        float a0 = 0.f, a1 = 0.f, a2 = 0.f, a3 = 0.f;
        int e = beg;
        for (; e + 8 <= end; e += 8) {
            int j0 = g_csr[e + 0], j1 = g_csr[e + 1];
            int j2 = g_csr[e + 2], j3 = g_csr[e + 3];
            int j4 = g_csr[e + 4], j5 = g_csr[e + 5];
            int j6 = g_csr[e + 6], j7 = g_csr[e + 7];
            if (VEC == 4) {
                float4 v0 = *(const float4*)(base + (size_t)j0 * HC);
                float4 v1 = *(const float4*)(base + (size_t)j1 * HC);
                float4 v2 = *(const float4*)(base + (size_t)j2 * HC);
                float4 v3 = *(const float4*)(base + (size_t)j3 * HC);
                float4 v4 = *(const float4*)(base + (size_t)j4 * HC);
                float4 v5 = *(const float4*)(base + (size_t)j5 * HC);
                float4 v6 = *(const float4*)(base + (size_t)j6 * HC);
                float4 v7 = *(const float4*)(base + (size_t)j7 * HC);
                a0 += (v0.x + v1.x) + (v2.x + v3.x) + (v4.x + v5.x) + (v6.x + v7.x);
                a1 += (v0.y + v1.y) + (v2.y + v3.y) + (v4.y + v5.y) + (v6.y + v7.y);
                a2 += (v0.z + v1.z) + (v2.z + v3.z) + (v4.z + v5.z) + (v6.z + v7.z);
                a3 += (v0.w + v1.w) + (v2.w + v3.w) + (v4.w + v5.w) + (v6.w + v7.w);
            } else {
                float2 v0 = *(const float2*)(base + (size_t)j0 * HC);
                float2 v1 = *(const float2*)(base + (size_t)j1 * HC);
                float2 v2 = *(const float2*)(base + (size_t)j2 * HC);
                float2 v3 = *(const float2*)(base + (size_t)j3 * HC);
                float2 v4 = *(const float2*)(base + (size_t)j4 * HC);
                float2 v5 = *(const float2*)(base + (size_t)j5 * HC);
                float2 v6 = *(const float2*)(base + (size_t)j6 * HC);
                float2 v7 = *(const float2*)(base + (size_t)j7 * HC);
                a0 += (v0.x + v1.x) + (v2.x + v3.x) + (v4.x + v5.x) + (v6.x + v7.x);
                a1 += (v0.y + v1.y) + (v2.y + v3.y) + (v4.y + v5.y) + (v6.y + v7.y);
            }
        }
        for (; e + 4 <= end; e += 4) {
            int j0 = g_csr[e + 0], j1 = g_csr[e + 1];
            int j2 = g_csr[e + 2], j3 = g_csr[e + 3];
            if (VEC == 4) {
                float4 v0 = *(const float4*)(base + (size_t)j0 * HC);
                float4 v1 = *(const float4*)(base + (size_t)j1 * HC);
                float4 v2 = *(const float4*)(base + (size_t)j2 * HC);
                float4 v3 = *(const float4*)(base + (size_t)j3 * HC);
                a0 += (v0.x + v1.x) + (v2.x + v3.x);
                a1 += (v0.y + v1.y) + (v2.y + v3.y);
                a2 += (v0.z + v1.z) + (v2.z + v3.z);
                a3 += (v0.w + v1.w) + (v2.w + v3.w);
            } else {
                float2 v0 = *(const float2*)(base + (size_t)j0 * HC);
                float2 v1 = *(const float2*)(base + (size_t)j1 * HC);
                float2 v2 = *(const float2*)(base + (size_t)j2 * HC);
                float2 v3 = *(const float2*)(base + (size_t)j3 * HC);
                a0 += (v0.x + v1.x) + (v2.x + v3.x);
                a1 += (v0.y + v1.y) + (v2.y + v3.y);
            }
        }
        for (; e < end; e++) {
            int j = g_csr[e];
            if (VEC == 4) {
                float4 v = *(const float4*)(base + (size_t)j * HC);
                a0 += v.x; a1 += v.y; a2 += v.z; a3 += v.w;
            } else {
                float2 v = *(const float2*)(base + (size_t)j * HC);
                a0 += v.x; a1 += v.y;
            }
        }

        float dinv = 1.f / (float)max(end - beg, 1);
        const float* hrp = hr + (size_t)node * HC + lane * VEC;
        float* yp = y + (size_t)node * HC + lane * VEC;
        float v[4];
        v[0] = a0 * dinv + hrp[0];
        v[1] = a1 * dinv + hrp[1];
        if (VEC == 4) {
            v[2] = a2 * dinv + hrp[2];
            v[3] = a3 * dinv + hrp[3];
            *(float4*)yp = make_float4(v[0], v[1], v[2], v[3]);
        } else {
            *(float2*)yp = make_float2(v[0], v[1]);
        }
        if (STATS) {
#pragma unroll
            for (int i = 0; i < VEC; i++) {
                atomicAdd(&ssum[lane * VEC + i], v[i]);
                atomicAdd(&ssq [lane * VEC + i], v[i] * v[i]);
            }
        }
    }

    if (STATS) {
        __syncthreads();
        if (t < HC) {
            atomicAdd(&g_sum[t], ssum[t]);
            atomicAdd(&g_sq [t], ssq [t]);
        }
    }
}

// ---------------- BN finalize: scale/shift from accumulated stats ----------
__global__ void k_bnfin(const float* __restrict__ gamma,
                        const float* __restrict__ beta, int n)
{
    int c = threadIdx.x;
    if (c < HMAX) {
        float inv_n = 1.f / (float)n;
        float mu  = g_sum[c] * inv_n;
        float var = fmaxf(g_sq[c] * inv_n - mu * mu, 0.f);
        float s   = gamma[c] * rsqrtf(var + c_eps);
        g_scale[c] = s;
        g_shift[c] = beta[c] - mu * s;
        g_sum[c] = 0.f;       // reset for next layer's stats
        g_sq [c] = 0.f;
    }
}

// ---------------- driver ----------------------------------------------------
extern "C" void kernel_launch(void* const* d_in, const int* in_sizes, int n_in,
                              void* d_out, int out_size)
{
    const float* x   = (const float*)d_in[0];
    const int*   ei  = (const int*)  d_in[1];
    const float* Wl0 = (const float*)d_in[2];
    const float* Wr0 = (const float*)d_in[3];
    const float* b0  = (const float*)d_in[4];
    const float* g0  = (const float*)d_in[5];
    const float* be0 = (const float*)d_in[6];
    const float* Wl1 = (const float*)d_in[7];
    const float* Wr1 = (const float*)d_in[8];
    const float* b1  = (const float*)d_in[9];
    const float* g1  = (const float*)d_in[10];
    const float* be1 = (const float*)d_in[11];
    const float* Wl2 = (const float*)d_in[12];
    const float* Wr2 = (const float*)d_in[13];
    const float* b2  = (const float*)d_in[14];

    const int n = in_sizes[0] / KDIM;
    const int e = in_sizes[1] / 2;
    const int* src = ei;
    const int* dst = ei + e;

    float *hl, *hr, *y, *scale, *shift;
    cudaGetSymbolAddress((void**)&hl,    g_hl);
    cudaGetSymbolAddress((void**)&hr,    g_hr);
    cudaGetSymbolAddress((void**)&y,     g_y);
    cudaGetSymbolAddress((void**)&scale, g_scale);
    cudaGetSymbolAddress((void**)&shift, g_shift);

    // CSR build
    k_zero<<<(n + 255) / 256, 256>>>(n);
    k_hist<<<(e + 511) / 512, 512>>>(dst, e);
    k_scan<<<1, 1024>>>(n);
    k_fill<<<(e + 511) / 512, 512>>>(src, dst, e);

    const int gb = (n + 127) / 128;     // GEMM blocks (128 rows each)
    const int ab = (n + 15) / 16;       // agg blocks (16 nodes each)

    // layer 0: SAGEConv(128->128) + BN + ReLU (BN+ReLU deferred to next load)
    k_gemm2<128><<<gb, 256>>>(x, Wl0, Wr0, b0, nullptr, nullptr, hl, hr, n);
    k_agg<128, true><<<ab, 512>>>(hl, hr, y, n);
    k_bnfin<<<1, 128>>>(g0, be0, n);

    // layer 1
    k_gemm2<128><<<gb, 256>>>(y, Wl1, Wr1, b1, scale, shift, hl, hr, n);
    k_agg<128, true><<<ab, 512>>>(hl, hr, y, n);
    k_bnfin<<<1, 128>>>(g1, be1, n);

    // layer 2: SAGEConv(128->64), no BN
    k_gemm2<64><<<gb, 256>>>(y, Wl2, Wr2, b2, scale, shift, hl, hr, n);
    k_agg<64, false><<<ab, 512>>>(hl, hr, (float*)d_out, n);
}

// round 9
// speedup vs baseline: 1.2223x; 1.2223x over previous
#include <cuda_runtime.h>
#include <cuda_fp16.h>

// Problem constants (shapes fixed by the dataset)
#define NMAX 50000
#define EMAX 1600000
#define KDIM 128          // inner dim of every GEMM (IN = H = 128)
#define HMAX 128
static __device__ __constant__ float c_eps = 1e-5f;

// ---------------- scratch (static device globals; no allocs allowed) -------
__device__ int    g_deg[NMAX];
__device__ int    g_rowptr[NMAX + 1];
__device__ int    g_cursor[NMAX];
__device__ int    g_csr[EMAX];
__device__ __half g_hl[NMAX * HMAX];      // fp16 messages (gathered by agg)
__device__ float  g_hr[NMAX * HMAX];
__device__ float  g_y [NMAX * HMAX];
__device__ float  g_sum[HMAX];
__device__ float  g_sq [HMAX];
__device__ float  g_scale[HMAX];
__device__ float  g_shift[HMAX];

// ---------------- CSR construction -----------------------------------------
__global__ void k_zero(int n) {
    int i = blockIdx.x * blockDim.x + threadIdx.x;
    if (i < n) g_deg[i] = 0;
    if (i < HMAX) { g_sum[i] = 0.f; g_sq[i] = 0.f; }
}

__global__ void k_hist(const int* __restrict__ dst, int e) {
    int i = blockIdx.x * blockDim.x + threadIdx.x;
    if (i < e) atomicAdd(&g_deg[dst[i]], 1);
}

// single-block exclusive scan over g_deg -> g_rowptr (and g_cursor).
// shfl-based warp scans: 4 block barriers per 1024-chunk instead of ~22.
__global__ void k_scan(int n) {
    __shared__ int wsum[32];
    __shared__ int carry_s;
    const int t = threadIdx.x;
    const int lane = t & 31;
    const int wid  = t >> 5;
    if (t == 0) carry_s = 0;
    __syncthreads();
    for (int base = 0; base < n; base += 1024) {
        int v = (base + t < n) ? g_deg[base + t] : 0;
        // warp inclusive scan
        int val = v;
#pragma unroll
        for (int off = 1; off < 32; off <<= 1) {
            int x = __shfl_up_sync(0xffffffffu, val, off);
            if (lane >= off) val += x;
        }
        if (lane == 31) wsum[wid] = val;
        __syncthreads();
        if (wid == 0) {
            int s = wsum[lane];
#pragma unroll
            for (int off = 1; off < 32; off <<= 1) {
                int x = __shfl_up_sync(0xffffffffu, s, off);
                if (lane >= off) s += x;
            }
            wsum[lane] = s;
        }
        __syncthreads();
        int prefix = (wid > 0) ? wsum[wid - 1] : 0;
        int incl   = val + prefix;          // inclusive scan within chunk
        int carry  = carry_s;
        if (base + t < n) {
            int ex = carry + incl - v;      // exclusive prefix
            g_rowptr[base + t] = ex;
            g_cursor[base + t] = ex;        // cursor pre-seeded at row start
        }
        __syncthreads();                    // all reads of carry_s/wsum done
        if (t == 1023) carry_s = carry + incl;
        __syncthreads();
    }
    if (t == 0) g_rowptr[n] = carry_s;
}

__global__ void k_fill(const int* __restrict__ src, const int* __restrict__ dst, int e) {
    int i = blockIdx.x * blockDim.x + threadIdx.x;
    if (i < e) {
        int p = atomicAdd(&g_cursor[dst[i]], 1);   // cursor holds absolute slot
        g_csr[p] = src[i];
    }
}

// ---------------- fused dual GEMM ------------------------------------------
// hl16 = fp16( act(X) @ Wl^T ) ; hr = act(X) @ Wr^T + bias  (fp32)
// act(x) = relu(x*scale[k] + shift[k]) when scale != null.
// Block tile: 128 rows x HOUT cols. Thread tile 8 x TN x 2. KT=16 (smem 25 KB).
// Register double-buffering overlaps next chunk's global loads with the FMAs.
template <int HOUT>
__global__ void __launch_bounds__(256)
k_gemm2(const float* __restrict__ X,
        const float* __restrict__ Wl, const float* __restrict__ Wr,
        const float* __restrict__ bias,
        const float* __restrict__ scale, const float* __restrict__ shift,
        __half* __restrict__ hl16, float* __restrict__ hr, int n)
{
    constexpr int TN = HOUT / 16;     // 8 (HOUT=128) or 4 (HOUT=64)
    constexpr int KT = 16;
    constexpr int XS = 128 + 4;
    constexpr int WS = HOUT + 4;
    constexpr int WLN = HOUT / 64;    // W-load iterations (2 or 1)
    __shared__ float Xs [KT * XS];
    __shared__ float Wsl[KT * WS];
    __shared__ float Wsr[KT * WS];

    const int t  = threadIdx.x;
    const int cg = t & 15;
    const int rg = t >> 4;
    const int r0 = blockIdx.x * 128;

    int xrow[2], xq[2];
#pragma unroll
    for (int l = 0; l < 2; l++) { int f = t + l * 256; xrow[l] = f >> 2; xq[l] = f & 3; }
    int wc[WLN], wq[WLN];
#pragma unroll
    for (int l = 0; l < WLN; l++) { int f = t + l * 256; wc[l] = f >> 2; wq[l] = f & 3; }

    float acc_l[8][TN], acc_r[8][TN];
#pragma unroll
    for (int i = 0; i < 8; i++)
#pragma unroll
        for (int j = 0; j < TN; j++) { acc_l[i][j] = 0.f; acc_r[i][j] = 0.f; }

    float4 xv[2], wlv[WLN], wrv[WLN];

    // prologue: chunk 0 into registers
#pragma unroll
    for (int l = 0; l < 2; l++) {
        int gr = r0 + xrow[l];
        xv[l] = make_float4(0.f, 0.f, 0.f, 0.f);
        if (gr < n) xv[l] = *(const float4*)(X + (size_t)gr * KDIM + xq[l] * 4);
    }
#pragma unroll
    for (int l = 0; l < WLN; l++) {
        wlv[l] = *(const float4*)(Wl + (size_t)wc[l] * KDIM + wq[l] * 4);
        wrv[l] = *(const float4*)(Wr + (size_t)wc[l] * KDIM + wq[l] * 4);
    }

    for (int k0 = 0; k0 < KDIM; k0 += KT) {
        // store current chunk's registers into smem (BN+ReLU fused on X)
#pragma unroll
        for (int l = 0; l < 2; l++) {
            float4 v = xv[l];
            if (scale) {
                int kb = k0 + xq[l] * 4;
                v.x = fmaxf(0.f, v.x * scale[kb + 0] + shift[kb + 0]);
                v.y = fmaxf(0.f, v.y * scale[kb + 1] + shift[kb + 1]);
                v.z = fmaxf(0.f, v.z * scale[kb + 2] + shift[kb + 2]);
                v.w = fmaxf(0.f, v.w * scale[kb + 3] + shift[kb + 3]);
            }
            int row = xrow[l], q = xq[l];
            Xs[(q * 4 + 0) * XS + row] = v.x;
            Xs[(q * 4 + 1) * XS + row] = v.y;
            Xs[(q * 4 + 2) * XS + row] = v.z;
            Xs[(q * 4 + 3) * XS + row] = v.w;
        }
#pragma unroll
        for (int l = 0; l < WLN; l++) {
            int c = wc[l], q = wq[l];
            Wsl[(q * 4 + 0) * WS + c] = wlv[l].x;
            Wsl[(q * 4 + 1) * WS + c] = wlv[l].y;
            Wsl[(q * 4 + 2) * WS + c] = wlv[l].z;
            Wsl[(q * 4 + 3) * WS + c] = wlv[l].w;
            Wsr[(q * 4 + 0) * WS + c] = wrv[l].x;
            Wsr[(q * 4 + 1) * WS + c] = wrv[l].y;
            Wsr[(q * 4 + 2) * WS + c] = wrv[l].z;
            Wsr[(q * 4 + 3) * WS + c] = wrv[l].w;
        }
        __syncthreads();

        // prefetch NEXT chunk (overlaps FMA loop)
        int kn = k0 + KT;
        if (kn < KDIM) {
#pragma unroll
            for (int l = 0; l < 2; l++) {
                int gr = r0 + xrow[l];
                xv[l] = make_float4(0.f, 0.f, 0.f, 0.f);
                if (gr < n) xv[l] = *(const float4*)(X + (size_t)gr * KDIM + kn + xq[l] * 4);
            }
#pragma unroll
            for (int l = 0; l < WLN; l++) {
                wlv[l] = *(const float4*)(Wl + (size_t)wc[l] * KDIM + kn + wq[l] * 4);
                wrv[l] = *(const float4*)(Wr + (size_t)wc[l] * KDIM + kn + wq[l] * 4);
            }
        }

        // FMA loop over current smem tile
#pragma unroll
        for (int kk = 0; kk < KT; kk++) {
            float a[8];
            const float4* ap = (const float4*)(Xs + kk * XS + rg * 8);
            float4 a0 = ap[0], a1 = ap[1];
            a[0]=a0.x; a[1]=a0.y; a[2]=a0.z; a[3]=a0.w;
            a[4]=a1.x; a[5]=a1.y; a[6]=a1.z; a[7]=a1.w;
            float wl[TN], wr[TN];
            const float4* wlp = (const float4*)(Wsl + kk * WS + cg * TN);
            const float4* wrp = (const float4*)(Wsr + kk * WS + cg * TN);
#pragma unroll
            for (int j4 = 0; j4 < TN / 4; j4++) {
                float4 v = wlp[j4];
                wl[j4*4+0]=v.x; wl[j4*4+1]=v.y; wl[j4*4+2]=v.z; wl[j4*4+3]=v.w;
                float4 u = wrp[j4];
                wr[j4*4+0]=u.x; wr[j4*4+1]=u.y; wr[j4*4+2]=u.z; wr[j4*4+3]=u.w;
            }
#pragma unroll
            for (int i = 0; i < 8; i++)
#pragma unroll
                for (int j = 0; j < TN; j++) {
                    acc_l[i][j] = fmaf(a[i], wl[j], acc_l[i][j]);
                    acc_r[i][j] = fmaf(a[i], wr[j], acc_r[i][j]);
                }
        }
        __syncthreads();
    }

    // epilogue: hl in fp16 (half2-packed 8B stores), hr in fp32
#pragma unroll
    for (int i = 0; i < 8; i++) {
        int row = r0 + rg * 8 + i;
        if (row < n) {
#pragma unroll
            for (int j4 = 0; j4 < TN / 4; j4++) {
                int c = cg * TN + j4 * 4;
                union { __half2 h[2]; uint2 u; } pk;
                pk.h[0] = __floats2half2_rn(acc_l[i][j4*4+0], acc_l[i][j4*4+1]);
                pk.h[1] = __floats2half2_rn(acc_l[i][j4*4+2], acc_l[i][j4*4+3]);
                *(uint2*)(hl16 + (size_t)row * HOUT + c) = pk.u;
                float4 u;
                u.x = acc_r[i][j4*4+0] + bias[c + 0];
                u.y = acc_r[i][j4*4+1] + bias[c + 1];
                u.z = acc_r[i][j4*4+2] + bias[c + 2];
                u.w = acc_r[i][j4*4+3] + bias[c + 3];
                *(float4*)(hr + (size_t)row * HOUT + c) = u;
            }
        }
    }
}

// ---------------- aggregation: y = mean_nbr(hl16) + hr ----------------------
// warp per node; lane owns HC/32 channels (4 or 2 halves per neighbor row).
// fp16 gather (half the L2 bytes), fp32 accumulation. 8/4/1 load ladder.
template <int HC, bool STATS>
__global__ void __launch_bounds__(512)
k_agg(const __half* __restrict__ hl16, const float* __restrict__ hr,
      float* __restrict__ y, int n)
{
    constexpr int VEC = HC / 32;   // 4 or 2 halves per lane per row
    __shared__ float ssum[HC];
    __shared__ float ssq [HC];
    const int t    = threadIdx.x;
    const int lane = t & 31;
    const int w    = t >> 5;

    if (STATS) {
        if (t < HC) { ssum[t] = 0.f; ssq[t] = 0.f; }
        __syncthreads();
    }

    int node = blockIdx.x * 16 + w;
    if (node < n) {
        int beg = g_rowptr[node];
        int end = g_rowptr[node + 1];
        const __half* base = hl16 + lane * VEC;

        float a0 = 0.f, a1 = 0.f, a2 = 0.f, a3 = 0.f;
        int e = beg;

        if (VEC == 4) {
            for (; e + 8 <= end; e += 8) {
                uint2 r[8];
#pragma unroll
                for (int q = 0; q < 8; q++) {
                    int j = g_csr[e + q];
                    r[q] = *(const uint2*)(base + (size_t)j * HC);
                }
#pragma unroll
                for (int q = 0; q < 8; q++) {
                    float2 f0 = __half22float2(*(__half2*)&r[q].x);
                    float2 f1 = __half22float2(*(__half2*)&r[q].y);
                    a0 += f0.x; a1 += f0.y; a2 += f1.x; a3 += f1.y;
                }
            }
            for (; e + 4 <= end; e += 4) {
                uint2 r[4];
#pragma unroll
                for (int q = 0; q < 4; q++) {
                    int j = g_csr[e + q];
                    r[q] = *(const uint2*)(base + (size_t)j * HC);
                }
#pragma unroll
                for (int q = 0; q < 4; q++) {
                    float2 f0 = __half22float2(*(__half2*)&r[q].x);
                    float2 f1 = __half22float2(*(__half2*)&r[q].y);
                    a0 += f0.x; a1 += f0.y; a2 += f1.x; a3 += f1.y;
                }
            }
            for (; e < end; e++) {
                int j = g_csr[e];
                uint2 rr = *(const uint2*)(base + (size_t)j * HC);
                float2 f0 = __half22float2(*(__half2*)&rr.x);
                float2 f1 = __half22float2(*(__half2*)&rr.y);
                a0 += f0.x; a1 += f0.y; a2 += f1.x; a3 += f1.y;
            }
        } else {
            for (; e + 8 <= end; e += 8) {
                unsigned r[8];
#pragma unroll
                for (int q = 0; q < 8; q++) {
                    int j = g_csr[e + q];
                    r[q] = *(const unsigned*)(base + (size_t)j * HC);
                }
#pragma unroll
                for (int q = 0; q < 8; q++) {
                    float2 f = __half22float2(*(__half2*)&r[q]);
                    a0 += f.x; a1 += f.y;
                }
            }
            for (; e + 4 <= end; e += 4) {
                unsigned r[4];
#pragma unroll
                for (int q = 0; q < 4; q++) {
                    int j = g_csr[e + q];
                    r[q] = *(const unsigned*)(base + (size_t)j * HC);
                }
#pragma unroll
                for (int q = 0; q < 4; q++) {
                    float2 f = __half22float2(*(__half2*)&r[q]);
                    a0 += f.x; a1 += f.y;
                }
            }
            for (; e < end; e++) {
                int j = g_csr[e];
                unsigned rr = *(const unsigned*)(base + (size_t)j * HC);
                float2 f = __half22float2(*(__half2*)&rr);
                a0 += f.x; a1 += f.y;
            }
        }

        float dinv = 1.f / (float)max(end - beg, 1);
        const float* hrp = hr + (size_t)node * HC + lane * VEC;
        float* yp = y + (size_t)node * HC + lane * VEC;
        float v[4];
        v[0] = a0 * dinv + hrp[0];
        v[1] = a1 * dinv + hrp[1];
        if (VEC == 4) {
            v[2] = a2 * dinv + hrp[2];
            v[3] = a3 * dinv + hrp[3];
            *(float4*)yp = make_float4(v[0], v[1], v[2], v[3]);
        } else {
            *(float2*)yp = make_float2(v[0], v[1]);
        }
        if (STATS) {
#pragma unroll
            for (int i = 0; i < VEC; i++) {
                atomicAdd(&ssum[lane * VEC + i], v[i]);
                atomicAdd(&ssq [lane * VEC + i], v[i] * v[i]);
            }
        }
    }

    if (STATS) {
        __syncthreads();
        if (t < HC) {
            atomicAdd(&g_sum[t], ssum[t]);
            atomicAdd(&g_sq [t], ssq [t]);
        }
    }
}

// ---------------- BN finalize: scale/shift from accumulated stats ----------
__global__ void k_bnfin(const float* __restrict__ gamma,
                        const float* __restrict__ beta, int n)
{
    int c = threadIdx.x;
    if (c < HMAX) {
        float inv_n = 1.f / (float)n;
        float mu  = g_sum[c] * inv_n;
        float var = fmaxf(g_sq[c] * inv_n - mu * mu, 0.f);
        float s   = gamma[c] * rsqrtf(var + c_eps);
        g_scale[c] = s;
        g_shift[c] = beta[c] - mu * s;
        g_sum[c] = 0.f;       // reset for next layer's stats
        g_sq [c] = 0.f;
    }
}

// ---------------- driver ----------------------------------------------------
extern "C" void kernel_launch(void* const* d_in, const int* in_sizes, int n_in,
                              void* d_out, int out_size)
{
    const float* x   = (const float*)d_in[0];
    const int*   ei  = (const int*)  d_in[1];
    const float* Wl0 = (const float*)d_in[2];
    const float* Wr0 = (const float*)d_in[3];
    const float* b0  = (const float*)d_in[4];
    const float* g0  = (const float*)d_in[5];
    const float* be0 = (const float*)d_in[6];
    const float* Wl1 = (const float*)d_in[7];
    const float* Wr1 = (const float*)d_in[8];
    const float* b1  = (const float*)d_in[9];
    const float* g1  = (const float*)d_in[10];
    const float* be1 = (const float*)d_in[11];
    const float* Wl2 = (const float*)d_in[12];
    const float* Wr2 = (const float*)d_in[13];
    const float* b2  = (const float*)d_in[14];

    const int n = in_sizes[0] / KDIM;
    const int e = in_sizes[1] / 2;
    const int* src = ei;
    const int* dst = ei + e;

    __half* hl;
    float *hr, *y, *scale, *shift;
    cudaGetSymbolAddress((void**)&hl,    g_hl);
    cudaGetSymbolAddress((void**)&hr,    g_hr);
    cudaGetSymbolAddress((void**)&y,     g_y);
    cudaGetSymbolAddress((void**)&scale, g_scale);
    cudaGetSymbolAddress((void**)&shift, g_shift);

    // CSR build
    k_zero<<<(n + 255) / 256, 256>>>(n);
    k_hist<<<(e + 511) / 512, 512>>>(dst, e);
    k_scan<<<1, 1024>>>(n);
    k_fill<<<(e + 511) / 512, 512>>>(src, dst, e);

    const int gb = (n + 127) / 128;     // GEMM blocks (128 rows each)
    const int ab = (n + 15) / 16;       // agg blocks (16 nodes each)

    // layer 0: SAGEConv(128->128) + BN + ReLU (BN+ReLU deferred to next load)
    k_gemm2<128><<<gb, 256>>>(x, Wl0, Wr0, b0, nullptr, nullptr, hl, hr, n);
    k_agg<128, true><<<ab, 512>>>(hl, hr, y, n);
    k_bnfin<<<1, 128>>>(g0, be0, n);

    // layer 1
    k_gemm2<128><<<gb, 256>>>(y, Wl1, Wr1, b1, scale, shift, hl, hr, n);
    k_agg<128, true><<<ab, 512>>>(hl, hr, y, n);
    k_bnfin<<<1, 128>>>(g1, be1, n);

    // layer 2: SAGEConv(128->64), no BN
    k_gemm2<64><<<gb, 256>>>(y, Wl2, Wr2, b2, scale, shift, hl, hr, n);
    k_agg<64, false><<<ab, 512>>>(hl, hr, (float*)d_out, n);
}

// round 11
// speedup vs baseline: 1.3703x; 1.1210x over previous
#include <cuda_runtime.h>
#include <cuda_fp16.h>
#include <cuda_bf16.h>
#include <cstdint>

// Problem constants (shapes fixed by the dataset)
#define NMAX 50000
#define EMAX 1600000
#define KDIM 128          // inner dim of every GEMM (IN = H = 128)
#define HMAX 128
static __device__ __constant__ float c_eps = 1e-5f;

// ---------------- scratch (static device globals; no allocs allowed) -------
__device__ int    g_deg[NMAX];
__device__ int    g_rowptr[NMAX + 1];
__device__ int    g_cursor[NMAX];
__device__ int    g_csr[EMAX];
__device__ __half g_hl[NMAX * HMAX];      // fp16 messages (gathered by agg)
__device__ float  g_hr[NMAX * HMAX];
__device__ float  g_y [NMAX * HMAX];
__device__ float  g_sum[HMAX];
__device__ float  g_sq [HMAX];
__device__ float  g_scale[HMAX];
__device__ float  g_shift[HMAX];

// ---------------- CSR construction -----------------------------------------
__global__ void k_zero(int n) {
    int i = blockIdx.x * blockDim.x + threadIdx.x;
    if (i < n) g_deg[i] = 0;
    if (i < HMAX) { g_sum[i] = 0.f; g_sq[i] = 0.f; }
}

__global__ void k_hist(const int* __restrict__ dst, int e) {
    int i = blockIdx.x * blockDim.x + threadIdx.x;
    if (i < e) atomicAdd(&g_deg[dst[i]], 1);
}

// single-block exclusive scan over g_deg -> g_rowptr (and g_cursor).
__global__ void k_scan(int n) {
    __shared__ int wsum[32];
    __shared__ int carry_s;
    const int t = threadIdx.x;
    const int lane = t & 31;
    const int wid  = t >> 5;
    if (t == 0) carry_s = 0;
    __syncthreads();
    for (int base = 0; base < n; base += 1024) {
        int v = (base + t < n) ? g_deg[base + t] : 0;
        int val = v;
#pragma unroll
        for (int off = 1; off < 32; off <<= 1) {
            int x = __shfl_up_sync(0xffffffffu, val, off);
            if (lane >= off) val += x;
        }
        if (lane == 31) wsum[wid] = val;
        __syncthreads();
        if (wid == 0) {
            int s = wsum[lane];
#pragma unroll
            for (int off = 1; off < 32; off <<= 1) {
                int x = __shfl_up_sync(0xffffffffu, s, off);
                if (lane >= off) s += x;
            }
            wsum[lane] = s;
        }
        __syncthreads();
        int prefix = (wid > 0) ? wsum[wid - 1] : 0;
        int incl   = val + prefix;
        int carry  = carry_s;
        if (base + t < n) {
            int ex = carry + incl - v;
            g_rowptr[base + t] = ex;
            g_cursor[base + t] = ex;
        }
        __syncthreads();
        if (t == 1023) carry_s = carry + incl;
        __syncthreads();
    }
    if (t == 0) g_rowptr[n] = carry_s;
}

__global__ void k_fill(const int* __restrict__ src, const int* __restrict__ dst, int e) {
    int i = blockIdx.x * blockDim.x + threadIdx.x;
    if (i < e) {
        int p = atomicAdd(&g_cursor[dst[i]], 1);
        g_csr[p] = src[i];
    }
}

// ---------------- split-bf16 helpers ---------------------------------------
__device__ __forceinline__ uint32_t pack2_bf16(float a, float b) {
    __nv_bfloat162 h = __floats2bfloat162_rn(a, b);
    return *reinterpret_cast<uint32_t*>(&h);
}

__device__ __forceinline__ void mma_bf16(float* c, const uint32_t* a, const uint32_t* b) {
    asm volatile(
        "mma.sync.aligned.m16n8k16.row.col.f32.bf16.bf16.f32 "
        "{%0,%1,%2,%3}, {%4,%5,%6,%7}, {%8,%9}, {%0,%1,%2,%3};\n"
        : "+f"(c[0]), "+f"(c[1]), "+f"(c[2]), "+f"(c[3])
        : "r"(a[0]), "r"(a[1]), "r"(a[2]), "r"(a[3]),
          "r"(b[0]), "r"(b[1]));
}

// ---------------- fused dual GEMM (tensor cores, split-bf16) ----------------
// hl16 = fp16( act(X) @ Wl^T ) ; hr = act(X) @ Wr^T + bias  (fp32)
// act(x) = relu(x*scale[k] + shift[k]) when scale != null.
// Split precision: v = hi + lo (two bf16); D += Ah*Bh + Ah*Bl + Al*Bh (fp32 acc).
// Block: 128 rows x HOUT cols, 8 warps x (16 rows x HOUT). k in chunks of 16.
// smem rows padded to 18 halves (9 words) -> conflict-light fragment loads.
template <int HOUT>
__global__ void __launch_bounds__(256)
k_gemm2(const float* __restrict__ X,
        const float* __restrict__ Wl, const float* __restrict__ Wr,
        const float* __restrict__ bias,
        const float* __restrict__ scale, const float* __restrict__ shift,
        __half* __restrict__ hl16, float* __restrict__ hr, int n)
{
    constexpr int NT = HOUT / 8;          // n-tiles per warp (16 or 8)
    constexpr int RS = 9;                 // row stride in u32 words (16 bf16 + pad)
    __shared__ uint32_t sXh[128 * RS], sXl[128 * RS];
    __shared__ uint32_t sWlh[HOUT * RS], sWll[HOUT * RS];
    __shared__ uint32_t sWrh[HOUT * RS], sWrl[HOUT * RS];

    const int t    = threadIdx.x;
    const int lane = t & 31;
    const int w    = t >> 5;              // warp 0..7
    const int g    = lane >> 2;           // group 0..7
    const int tig  = lane & 3;            // thread-in-group 0..3
    const int r0   = blockIdx.x * 128;

    float accL[NT][4], accR[NT][4];
#pragma unroll
    for (int j = 0; j < NT; j++)
#pragma unroll
        for (int q = 0; q < 4; q++) { accL[j][q] = 0.f; accR[j][q] = 0.f; }

    // loader coordinates
    const int xrow = t >> 1;              // 0..127
    const int xseg = t & 1;               // 0/1: cols [seg*8, seg*8+8)
    const int wmat = t / HOUT;            // 0 = Wl, 1 = Wr (only t < 2*HOUT active)
    const int wrow = t % HOUT;

    for (int k0 = 0; k0 < KDIM; k0 += 16) {
        // ---- X tile: 128 x 16 fp32 -> BN/ReLU -> split bf16 hi/lo
        {
            int gr = r0 + xrow;
            float f[8];
            if (gr < n) {
                const float* xp = X + (size_t)gr * KDIM + k0 + xseg * 8;
                float4 v1 = *(const float4*)(xp);
                float4 v2 = *(const float4*)(xp + 4);
                f[0]=v1.x; f[1]=v1.y; f[2]=v1.z; f[3]=v1.w;
                f[4]=v2.x; f[5]=v2.y; f[6]=v2.z; f[7]=v2.w;
            } else {
#pragma unroll
                for (int i = 0; i < 8; i++) f[i] = 0.f;
            }
            if (scale) {
                int kb = k0 + xseg * 8;
#pragma unroll
                for (int i = 0; i < 8; i++)
                    f[i] = fmaxf(0.f, f[i] * scale[kb + i] + shift[kb + i]);
            }
            int base = xrow * RS + xseg * 4;
#pragma unroll
            for (int p = 0; p < 4; p++) {
                float f0 = f[2*p], f1 = f[2*p+1];
                __nv_bfloat16 h0 = __float2bfloat16_rn(f0);
                __nv_bfloat16 h1 = __float2bfloat16_rn(f1);
                float l0 = f0 - __bfloat162float(h0);
                float l1 = f1 - __bfloat162float(h1);
                __nv_bfloat162 hh; hh.x = h0; hh.y = h1;
                sXh[base + p] = *reinterpret_cast<uint32_t*>(&hh);
                sXl[base + p] = pack2_bf16(l0, l1);
            }
        }
        // ---- W tiles: (Wl,Wr) HOUT x 16 fp32 -> split bf16 hi/lo
        if (t < 2 * HOUT) {
            const float* wp = (wmat ? Wr : Wl) + (size_t)wrow * KDIM + k0;
            float4 v1 = *(const float4*)(wp);
            float4 v2 = *(const float4*)(wp + 4);
            float4 v3 = *(const float4*)(wp + 8);
            float4 v4 = *(const float4*)(wp + 12);
            float f[16] = {v1.x,v1.y,v1.z,v1.w, v2.x,v2.y,v2.z,v2.w,
                           v3.x,v3.y,v3.z,v3.w, v4.x,v4.y,v4.z,v4.w};
            uint32_t* dh = wmat ? sWrh : sWlh;
            uint32_t* dl = wmat ? sWrl : sWll;
            int base = wrow * RS;
#pragma unroll
            for (int p = 0; p < 8; p++) {
                float f0 = f[2*p], f1 = f[2*p+1];
                __nv_bfloat16 h0 = __float2bfloat16_rn(f0);
                __nv_bfloat16 h1 = __float2bfloat16_rn(f1);
                float l0 = f0 - __bfloat162float(h0);
                float l1 = f1 - __bfloat162float(h1);
                __nv_bfloat162 hh; hh.x = h0; hh.y = h1;
                dh[base + p] = *reinterpret_cast<uint32_t*>(&hh);
                dl[base + p] = pack2_bf16(l0, l1);
            }
        }
        __syncthreads();

        // ---- mma: each warp does rows [w*16, w*16+16) x all HOUT cols
        uint32_t ah[4], al[4];
        {
            int ra = (w * 16 + g) * RS;
            int rb = (w * 16 + g + 8) * RS;
            ah[0] = sXh[ra + tig];     ah[1] = sXh[rb + tig];
            ah[2] = sXh[ra + tig + 4]; ah[3] = sXh[rb + tig + 4];
            al[0] = sXl[ra + tig];     al[1] = sXl[rb + tig];
            al[2] = sXl[ra + tig + 4]; al[3] = sXl[rb + tig + 4];
        }
#pragma unroll
        for (int j = 0; j < NT; j++) {
            int rb = (j * 8 + g) * RS + tig;
            uint32_t bh[2], bl[2];
            bh[0] = sWlh[rb]; bh[1] = sWlh[rb + 4];
            bl[0] = sWll[rb]; bl[1] = sWll[rb + 4];
            mma_bf16(accL[j], ah, bh);
            mma_bf16(accL[j], ah, bl);
            mma_bf16(accL[j], al, bh);
            bh[0] = sWrh[rb]; bh[1] = sWrh[rb + 4];
            bl[0] = sWrl[rb]; bl[1] = sWrl[rb + 4];
            mma_bf16(accR[j], ah, bh);
            mma_bf16(accR[j], ah, bl);
            mma_bf16(accR[j], al, bh);
        }
        __syncthreads();
    }

    // ---- epilogue: C frag (r=g / g+8, c=2*tig, 2*tig+1)
    {
        int rowA = r0 + w * 16 + g;
        int rowB = rowA + 8;
#pragma unroll
        for (int j = 0; j < NT; j++) {
            int c = j * 8 + 2 * tig;
            float b0 = bias[c], b1 = bias[c + 1];
            if (rowA < n) {
                *(__half2*)(hl16 + (size_t)rowA * HOUT + c) =
                    __floats2half2_rn(accL[j][0], accL[j][1]);
                *(float2*)(hr + (size_t)rowA * HOUT + c) =
                    make_float2(accR[j][0] + b0, accR[j][1] + b1);
            }
            if (rowB < n) {
                *(__half2*)(hl16 + (size_t)rowB * HOUT + c) =
                    __floats2half2_rn(accL[j][2], accL[j][3]);
                *(float2*)(hr + (size_t)rowB * HOUT + c) =
                    make_float2(accR[j][2] + b0, accR[j][3] + b1);
            }
        }
    }
}

// ---------------- aggregation: y = mean_nbr(hl16) + hr ----------------------
template <int HC, bool STATS>
__global__ void __launch_bounds__(512)
k_agg(const __half* __restrict__ hl16, const float* __restrict__ hr,
      float* __restrict__ y, int n)
{
    constexpr int VEC = HC / 32;   // 4 or 2 halves per lane per row
    __shared__ float ssum[HC];
    __shared__ float ssq [HC];
    const int t    = threadIdx.x;
    const int lane = t & 31;
    const int w    = t >> 5;

    if (STATS) {
        if (t < HC) { ssum[t] = 0.f; ssq[t] = 0.f; }
        __syncthreads();
    }

    int node = blockIdx.x * 16 + w;
    if (node < n) {
        int beg = g_rowptr[node];
        int end = g_rowptr[node + 1];
        const __half* base = hl16 + lane * VEC;

        float a0 = 0.f, a1 = 0.f, a2 = 0.f, a3 = 0.f;
        int e = beg;

        if (VEC == 4) {
            for (; e + 8 <= end; e += 8) {
                uint2 r[8];
#pragma unroll
                for (int q = 0; q < 8; q++) {
                    int j = g_csr[e + q];
                    r[q] = *(const uint2*)(base + (size_t)j * HC);
                }
#pragma unroll
                for (int q = 0; q < 8; q++) {
                    float2 f0 = __half22float2(*(__half2*)&r[q].x);
                    float2 f1 = __half22float2(*(__half2*)&r[q].y);
                    a0 += f0.x; a1 += f0.y; a2 += f1.x; a3 += f1.y;
                }
            }
            for (; e + 4 <= end; e += 4) {
                uint2 r[4];
#pragma unroll
                for (int q = 0; q < 4; q++) {
                    int j = g_csr[e + q];
                    r[q] = *(const uint2*)(base + (size_t)j * HC);
                }
#pragma unroll
                for (int q = 0; q < 4; q++) {
                    float2 f0 = __half22float2(*(__half2*)&r[q].x);
                    float2 f1 = __half22float2(*(__half2*)&r[q].y);
                    a0 += f0.x; a1 += f0.y; a2 += f1.x; a3 += f1.y;
                }
            }
            for (; e < end; e++) {
                int j = g_csr[e];
                uint2 rr = *(const uint2*)(base + (size_t)j * HC);
                float2 f0 = __half22float2(*(__half2*)&rr.x);
                float2 f1 = __half22float2(*(__half2*)&rr.y);
                a0 += f0.x; a1 += f0.y; a2 += f1.x; a3 += f1.y;
            }
        } else {
            for (; e + 8 <= end; e += 8) {
                unsigned r[8];
#pragma unroll
                for (int q = 0; q < 8; q++) {
                    int j = g_csr[e + q];
                    r[q] = *(const unsigned*)(base + (size_t)j * HC);
                }
#pragma unroll
                for (int q = 0; q < 8; q++) {
                    float2 f = __half22float2(*(__half2*)&r[q]);
                    a0 += f.x; a1 += f.y;
                }
            }
            for (; e + 4 <= end; e += 4) {
                unsigned r[4];
#pragma unroll
                for (int q = 0; q < 4; q++) {
                    int j = g_csr[e + q];
                    r[q] = *(const unsigned*)(base + (size_t)j * HC);
                }
#pragma unroll
                for (int q = 0; q < 4; q++) {
                    float2 f = __half22float2(*(__half2*)&r[q]);
                    a0 += f.x; a1 += f.y;
                }
            }
            for (; e < end; e++) {
                int j = g_csr[e];
                unsigned rr = *(const unsigned*)(base + (size_t)j * HC);
                float2 f = __half22float2(*(__half2*)&rr);
                a0 += f.x; a1 += f.y;
            }
        }

        float dinv = 1.f / (float)max(end - beg, 1);
        const float* hrp = hr + (size_t)node * HC + lane * VEC;
        float* yp = y + (size_t)node * HC + lane * VEC;
        float v[4];
        v[0] = a0 * dinv + hrp[0];
        v[1] = a1 * dinv + hrp[1];
        if (VEC == 4) {
            v[2] = a2 * dinv + hrp[2];
            v[3] = a3 * dinv + hrp[3];
            *(float4*)yp = make_float4(v[0], v[1], v[2], v[3]);
        } else {
            *(float2*)yp = make_float2(v[0], v[1]);
        }
        if (STATS) {
#pragma unroll
            for (int i = 0; i < VEC; i++) {
                atomicAdd(&ssum[lane * VEC + i], v[i]);
                atomicAdd(&ssq [lane * VEC + i], v[i] * v[i]);
            }
        }
    }

    if (STATS) {
        __syncthreads();
        if (t < HC) {
            atomicAdd(&g_sum[t], ssum[t]);
            atomicAdd(&g_sq [t], ssq [t]);
        }
    }
}

// ---------------- BN finalize: scale/shift from accumulated stats ----------
__global__ void k_bnfin(const float* __restrict__ gamma,
                        const float* __restrict__ beta, int n)
{
    int c = threadIdx.x;
    if (c < HMAX) {
        float inv_n = 1.f / (float)n;
        float mu  = g_sum[c] * inv_n;
        float var = fmaxf(g_sq[c] * inv_n - mu * mu, 0.f);
        float s   = gamma[c] * rsqrtf(var + c_eps);
        g_scale[c] = s;
        g_shift[c] = beta[c] - mu * s;
        g_sum[c] = 0.f;
        g_sq [c] = 0.f;
    }
}

// ---------------- driver ----------------------------------------------------
extern "C" void kernel_launch(void* const* d_in, const int* in_sizes, int n_in,
                              void* d_out, int out_size)
{
    const float* x   = (const float*)d_in[0];
    const int*   ei  = (const int*)  d_in[1];
    const float* Wl0 = (const float*)d_in[2];
    const float* Wr0 = (const float*)d_in[3];
    const float* b0  = (const float*)d_in[4];
    const float* g0  = (const float*)d_in[5];
    const float* be0 = (const float*)d_in[6];
    const float* Wl1 = (const float*)d_in[7];
    const float* Wr1 = (const float*)d_in[8];
    const float* b1  = (const float*)d_in[9];
    const float* g1  = (const float*)d_in[10];
    const float* be1 = (const float*)d_in[11];
    const float* Wl2 = (const float*)d_in[12];
    const float* Wr2 = (const float*)d_in[13];
    const float* b2  = (const float*)d_in[14];

    const int n = in_sizes[0] / KDIM;
    const int e = in_sizes[1] / 2;
    const int* src = ei;
    const int* dst = ei + e;

    __half* hl;
    float *hr, *y, *scale, *shift;
    cudaGetSymbolAddress((void**)&hl,    g_hl);
    cudaGetSymbolAddress((void**)&hr,    g_hr);
    cudaGetSymbolAddress((void**)&y,     g_y);
    cudaGetSymbolAddress((void**)&scale, g_scale);
    cudaGetSymbolAddress((void**)&shift, g_shift);

    // CSR build
    k_zero<<<(n + 255) / 256, 256>>>(n);
    k_hist<<<(e + 511) / 512, 512>>>(dst, e);
    k_scan<<<1, 1024>>>(n);
    k_fill<<<(e + 511) / 512, 512>>>(src, dst, e);

    const int gb = (n + 127) / 128;     // GEMM blocks (128 rows each)
    const int ab = (n + 15) / 16;       // agg blocks (16 nodes each)

    // layer 0: SAGEConv(128->128) + BN + ReLU (BN+ReLU deferred to next load)
    k_gemm2<128><<<gb, 256>>>(x, Wl0, Wr0, b0, nullptr, nullptr, hl, hr, n);
    k_agg<128, true><<<ab, 512>>>(hl, hr, y, n);
    k_bnfin<<<1, 128>>>(g0, be0, n);

    // layer 1
    k_gemm2<128><<<gb, 256>>>(y, Wl1, Wr1, b1, scale, shift, hl, hr, n);
    k_agg<128, true><<<ab, 512>>>(hl, hr, y, n);
    k_bnfin<<<1, 128>>>(g1, be1, n);

    // layer 2: SAGEConv(128->64), no BN
    k_gemm2<64><<<gb, 256>>>(y, Wl2, Wr2, b2, scale, shift, hl, hr, n);
    k_agg<64, false><<<ab, 512>>>(hl, hr, (float*)d_out, n);
}